// round 13
// baseline (speedup 1.0000x reference)
#include <cuda_runtime.h>
#include <cuda_fp16.h>
#include <cuda_bf16.h>
#include <cstdint>

// ---------------------------------------------------------------------------
// MultiResImplicitFeature R13: progressive v8 WRITE-BACK stores (L2 merges
// partial rows regardless of timing) + launch_bounds(256,4) for occupancy,
// + 3-sincos harmonic Fourier path.
//  - grids: pair-duplicated fp16 channel-last entries (32 B):
//      entry(z,y,x) = [8ch of voxel x | 8ch of voxel min(x+1,R-1)]
//    trilerp = 4 x ld.global.v8.f32
//  - output: 7 x st.global.v8.f32 per row, emitted as results are ready.
// ---------------------------------------------------------------------------

static constexpr int RES0 = 16, RES1 = 32, RES2 = 64, RES3 = 128;
static constexpr int S0 = RES0*RES0*RES0;
static constexpr int S1 = RES1*RES1*RES1;
static constexpr int S2 = RES2*RES2*RES2;
static constexpr int S3 = RES3*RES3*RES3;
static constexpr long long OFF0 = 0;
static constexpr long long OFF1 = (long long)S0*8;
static constexpr long long OFF2 = OFF1 + (long long)S1*8;
static constexpr long long OFF3 = OFF2 + (long long)S2*8;
static constexpr long long GTOTAL = OFF3 + (long long)S3*8;   // 76.7 MB

__device__ __align__(256) uint32_t g_grids[GTOTAL];

__device__ __forceinline__ void ldg256(const uint32_t* p, uint32_t r[8]) {
    asm volatile("ld.global.v8.f32 {%0,%1,%2,%3,%4,%5,%6,%7}, [%8];"
                 : "=r"(r[0]), "=r"(r[1]), "=r"(r[2]), "=r"(r[3]),
                   "=r"(r[4]), "=r"(r[5]), "=r"(r[6]), "=r"(r[7])
                 : "l"(p));
}

// Write-back (default) 256-bit store: partial-row writes merge in L2.
__device__ __forceinline__ void stg256(float* p, const float* v) {
    asm volatile("st.global.v8.f32 [%0], {%1,%2,%3,%4,%5,%6,%7,%8};"
                 :: "l"(p), "f"(v[0]), "f"(v[1]), "f"(v[2]), "f"(v[3]),
                    "f"(v[4]), "f"(v[5]), "f"(v[6]), "f"(v[7])
                 : "memory");
}

// ---------------- fused transpose (one launch, all grids) -----------------

template <int R>
__device__ __forceinline__ void do_transpose(const float* __restrict__ in,
                                             uint32_t* __restrict__ out, int i) {
    constexpr int S = R * R * R;
    int x = i & (R - 1);
    int i2 = (x < R - 1) ? i + 1 : i;
    __half h[16];
#pragma unroll
    for (int c = 0; c < 8; c++) {
        h[c]     = __float2half(__ldcs(in + (long long)c * S + i));
        h[8 + c] = __float2half(__ldcs(in + (long long)c * S + i2));
    }
    uint4* dst = reinterpret_cast<uint4*>(out + (long long)i * 8);
    const uint4* src = reinterpret_cast<const uint4*>(h);
    dst[0] = src[0];
    dst[1] = src[1];
}

static constexpr int TTOT = S3 + S2 + S1 + S0;

__global__ void __launch_bounds__(256)
fused_transpose_kernel(const float* __restrict__ g0, const float* __restrict__ g1,
                       const float* __restrict__ g2, const float* __restrict__ g3) {
    int u = blockIdx.x * blockDim.x + threadIdx.x;
    if (u < S3) {
        do_transpose<RES3>(g3, g_grids + OFF3, u);
    } else if (u < S3 + S2) {
        do_transpose<RES2>(g2, g_grids + OFF2, u - S3);
    } else if (u < S3 + S2 + S1) {
        do_transpose<RES1>(g1, g_grids + OFF1, u - S3 - S2);
    } else if (u < TTOT) {
        do_transpose<RES0>(g0, g_grids + OFF0, u - S3 - S2 - S1);
    }
}

// ---------------- main kernel ---------------------------------------------

struct TLerp {
    const uint32_t* a[4];
    float wzy[4];
    float wx;
};

template <int R>
__device__ __forceinline__ TLerp prep(const uint32_t* __restrict__ g,
                                      float px, float py, float pz) {
    const float scale = 0.5f * (float)(R - 1);
    float cx = (px + 1.0f) * scale;
    float cy = (py + 1.0f) * scale;
    float cz = (pz + 1.0f) * scale;
    float fx = floorf(cx), fy = floorf(cy), fz = floorf(cz);
    int x0 = (int)fx; x0 = max(0, min(x0, R - 1));
    int y0 = (int)fy; y0 = max(0, min(y0, R - 1));
    int z0 = (int)fz; z0 = max(0, min(z0, R - 1));
    int y1 = min(y0 + 1, R - 1);
    int z1 = min(z0 + 1, R - 1);
    float wx = cx - fx, wy = cy - fy, wz = cz - fz;

    TLerp t;
    t.wx = wx;
    long long b00 = ((long long)z0 * R + y0) * R + x0;
    long long b01 = ((long long)z0 * R + y1) * R + x0;
    long long b10 = ((long long)z1 * R + y0) * R + x0;
    long long b11 = ((long long)z1 * R + y1) * R + x0;
    t.a[0] = g + (b00 << 3);
    t.a[1] = g + (b01 << 3);
    t.a[2] = g + (b10 << 3);
    t.a[3] = g + (b11 << 3);
    t.wzy[0] = (1.0f - wz) * (1.0f - wy);
    t.wzy[1] = (1.0f - wz) * wy;
    t.wzy[2] = wz * (1.0f - wy);
    t.wzy[3] = wz * wy;
    return t;
}

__device__ __forceinline__ void load4(const TLerp& t, uint32_t r[4][8]) {
#pragma unroll
    for (int c = 0; c < 4; c++) ldg256(t.a[c], r[c]);
}

__device__ __forceinline__ void accum4(const TLerp& t, const uint32_t r[4][8],
                                       float* __restrict__ acc) {
    float wxl = 1.0f - t.wx;
    float wxr = t.wx;
#pragma unroll
    for (int c = 0; c < 4; c++) {
        float wl = t.wzy[c] * wxl;
        float wr = t.wzy[c] * wxr;
#pragma unroll
        for (int k = 0; k < 4; k++) {
            float2 a = __half22float2(*reinterpret_cast<const __half2*>(&r[c][k]));
            float2 b = __half22float2(*reinterpret_cast<const __half2*>(&r[c][4 + k]));
            acc[2*k]   = fmaf(wl, a.x, fmaf(wr, b.x, acc[2*k]));
            acc[2*k+1] = fmaf(wl, a.y, fmaf(wr, b.y, acc[2*k+1]));
        }
    }
}

__global__ void __launch_bounds__(256, 4)
mrif_main_kernel(const float* __restrict__ x, float* __restrict__ out, int n) {
    int i = blockIdx.x * blockDim.x + threadIdx.x;
    if (i >= n) return;

    float px = __ldg(x + 3LL * i + 0);
    float py = __ldg(x + 3LL * i + 1);
    float pz = __ldg(x + 3LL * i + 2);

    float* orow = out + (long long)i * 56;

    // Addresses for all four grids (pure ALU).
    TLerp t0 = prep<RES0>(g_grids + OFF0, px, py, pz);
    TLerp t1 = prep<RES1>(g_grids + OFF1, px, py, pz);
    TLerp t2 = prep<RES2>(g_grids + OFF2, px, py, pz);
    TLerp t3 = prep<RES3>(g_grids + OFF3, px, py, pz);

    // First load wave (grids 0,1) in flight during sincos.
    uint32_t r0[4][8], r1[4][8];
    load4(t0, r0);
    load4(t1, r1);

    // Fourier features: 3 sincos + harmonic recurrences, stored immediately.
    {
        const float HPI = 1.57079632679489662f;
        float p[3] = {px, py, pz};
        float sc[24];
#pragma unroll
        for (int d = 0; d < 3; d++) {
            float s1, c1;
            __sincosf(HPI * p[d], &s1, &c1);
            float s2 = 2.0f * s1 * c1;
            float c2 = fmaf(-2.0f * s1, s1, 1.0f);
            float s3 = fmaf(s2, c1, c2 * s1);
            float c3 = fmaf(c2, c1, -s2 * s1);
            float s4 = 2.0f * s2 * c2;
            float c4 = fmaf(-2.0f * s2, s2, 1.0f);
            sc[0 + d]  = s1;  sc[3 + d]  = s2;  sc[6 + d]  = s3;  sc[9 + d]  = s4;
            sc[12 + d] = c1;  sc[15 + d] = c2;  sc[18 + d] = c3;  sc[21 + d] = c4;
        }
        stg256(orow + 0,  sc + 0);
        stg256(orow + 8,  sc + 8);
        stg256(orow + 16, sc + 16);
    }

    // Second wave + consumption, each grid stored as soon as it's reduced.
    float f[8];
    uint32_t r2[4][8];
    load4(t2, r2);
#pragma unroll
    for (int c = 0; c < 8; c++) f[c] = 0.0f;
    accum4(t0, r0, f);
    stg256(orow + 24, f);

    uint32_t r3[4][8];
    load4(t3, r3);
#pragma unroll
    for (int c = 0; c < 8; c++) f[c] = 0.0f;
    accum4(t1, r1, f);
    stg256(orow + 32, f);

#pragma unroll
    for (int c = 0; c < 8; c++) f[c] = 0.0f;
    accum4(t2, r2, f);
    stg256(orow + 40, f);

#pragma unroll
    for (int c = 0; c < 8; c++) f[c] = 0.0f;
    accum4(t3, r3, f);
    stg256(orow + 48, f);
}

extern "C" void kernel_launch(void* const* d_in, const int* in_sizes, int n_in,
                              void* d_out, int out_size) {
    const float* x  = (const float*)d_in[0];
    const float* g0 = (const float*)d_in[1];
    const float* g1 = (const float*)d_in[2];
    const float* g2 = (const float*)d_in[3];
    const float* g3 = (const float*)d_in[4];
    float* out = (float*)d_out;

    int n = in_sizes[0] / 3;

    const int TT = 256;
    fused_transpose_kernel<<<(TTOT + TT - 1) / TT, TT>>>(g0, g1, g2, g3);
    mrif_main_kernel<<<(n + 255) / 256, 256>>>(x, out, n);
}

// round 14
// speedup vs baseline: 1.5471x; 1.5471x over previous
#include <cuda_runtime.h>
#include <cuda_fp16.h>
#include <cuda_bf16.h>
#include <cstdint>

// ---------------------------------------------------------------------------
// MultiResImplicitFeature R14: split the point work into two low-register
// kernels so occupancy (not intra-thread MLP) hides gather latency.
//  Kernel A: sincos + grid0 + grid1 -> cols 0..39  (5 consecutive .cs v8)
//  Kernel B: grid2 + grid3          -> cols 40..55 (2 consecutive .cs v8)
//  Both: single load-wave per grid (4 x ld.global.v8), pair-duplicated fp16
//  channel-last grid entries (32 B).
// ---------------------------------------------------------------------------

static constexpr int RES0 = 16, RES1 = 32, RES2 = 64, RES3 = 128;
static constexpr int S0 = RES0*RES0*RES0;
static constexpr int S1 = RES1*RES1*RES1;
static constexpr int S2 = RES2*RES2*RES2;
static constexpr int S3 = RES3*RES3*RES3;
static constexpr long long OFF0 = 0;
static constexpr long long OFF1 = (long long)S0*8;
static constexpr long long OFF2 = OFF1 + (long long)S1*8;
static constexpr long long OFF3 = OFF2 + (long long)S2*8;
static constexpr long long GTOTAL = OFF3 + (long long)S3*8;   // 76.7 MB

__device__ __align__(256) uint32_t g_grids[GTOTAL];

__device__ __forceinline__ void ldg256(const uint32_t* p, uint32_t r[8]) {
    asm volatile("ld.global.v8.f32 {%0,%1,%2,%3,%4,%5,%6,%7}, [%8];"
                 : "=r"(r[0]), "=r"(r[1]), "=r"(r[2]), "=r"(r[3]),
                   "=r"(r[4]), "=r"(r[5]), "=r"(r[6]), "=r"(r[7])
                 : "l"(p));
}

__device__ __forceinline__ void stg256cs(float* p, const float* v) {
    asm volatile("st.global.cs.v8.f32 [%0], {%1,%2,%3,%4,%5,%6,%7,%8};"
                 :: "l"(p), "f"(v[0]), "f"(v[1]), "f"(v[2]), "f"(v[3]),
                    "f"(v[4]), "f"(v[5]), "f"(v[6]), "f"(v[7])
                 : "memory");
}

// ---------------- fused transpose (one launch, all grids) -----------------

template <int R>
__device__ __forceinline__ void do_transpose(const float* __restrict__ in,
                                             uint32_t* __restrict__ out, int i) {
    constexpr int S = R * R * R;
    int x = i & (R - 1);
    int i2 = (x < R - 1) ? i + 1 : i;
    __half h[16];
#pragma unroll
    for (int c = 0; c < 8; c++) {
        h[c]     = __float2half(__ldcs(in + (long long)c * S + i));
        h[8 + c] = __float2half(__ldcs(in + (long long)c * S + i2));
    }
    uint4* dst = reinterpret_cast<uint4*>(out + (long long)i * 8);
    const uint4* src = reinterpret_cast<const uint4*>(h);
    dst[0] = src[0];
    dst[1] = src[1];
}

static constexpr int TTOT = S3 + S2 + S1 + S0;

__global__ void __launch_bounds__(256)
fused_transpose_kernel(const float* __restrict__ g0, const float* __restrict__ g1,
                       const float* __restrict__ g2, const float* __restrict__ g3) {
    int u = blockIdx.x * blockDim.x + threadIdx.x;
    if (u < S3) {
        do_transpose<RES3>(g3, g_grids + OFF3, u);
    } else if (u < S3 + S2) {
        do_transpose<RES2>(g2, g_grids + OFF2, u - S3);
    } else if (u < S3 + S2 + S1) {
        do_transpose<RES1>(g1, g_grids + OFF1, u - S3 - S2);
    } else if (u < TTOT) {
        do_transpose<RES0>(g0, g_grids + OFF0, u - S3 - S2 - S1);
    }
}

// ---------------- trilerp helpers -----------------------------------------

struct TLerp {
    const uint32_t* a[4];
    float wzy[4];
    float wx;
};

template <int R>
__device__ __forceinline__ TLerp prep(const uint32_t* __restrict__ g,
                                      float px, float py, float pz) {
    const float scale = 0.5f * (float)(R - 1);
    float cx = (px + 1.0f) * scale;
    float cy = (py + 1.0f) * scale;
    float cz = (pz + 1.0f) * scale;
    float fx = floorf(cx), fy = floorf(cy), fz = floorf(cz);
    int x0 = (int)fx; x0 = max(0, min(x0, R - 1));
    int y0 = (int)fy; y0 = max(0, min(y0, R - 1));
    int z0 = (int)fz; z0 = max(0, min(z0, R - 1));
    int y1 = min(y0 + 1, R - 1);
    int z1 = min(z0 + 1, R - 1);
    float wx = cx - fx, wy = cy - fy, wz = cz - fz;

    TLerp t;
    t.wx = wx;
    long long b00 = ((long long)z0 * R + y0) * R + x0;
    long long b01 = ((long long)z0 * R + y1) * R + x0;
    long long b10 = ((long long)z1 * R + y0) * R + x0;
    long long b11 = ((long long)z1 * R + y1) * R + x0;
    t.a[0] = g + (b00 << 3);
    t.a[1] = g + (b01 << 3);
    t.a[2] = g + (b10 << 3);
    t.a[3] = g + (b11 << 3);
    t.wzy[0] = (1.0f - wz) * (1.0f - wy);
    t.wzy[1] = (1.0f - wz) * wy;
    t.wzy[2] = wz * (1.0f - wy);
    t.wzy[3] = wz * wy;
    return t;
}

__device__ __forceinline__ void load4(const TLerp& t, uint32_t r[4][8]) {
#pragma unroll
    for (int c = 0; c < 4; c++) ldg256(t.a[c], r[c]);
}

__device__ __forceinline__ void accum4(const TLerp& t, const uint32_t r[4][8],
                                       float* __restrict__ acc) {
    float wxl = 1.0f - t.wx;
    float wxr = t.wx;
#pragma unroll
    for (int c = 0; c < 4; c++) {
        float wl = t.wzy[c] * wxl;
        float wr = t.wzy[c] * wxr;
#pragma unroll
        for (int k = 0; k < 4; k++) {
            float2 a = __half22float2(*reinterpret_cast<const __half2*>(&r[c][k]));
            float2 b = __half22float2(*reinterpret_cast<const __half2*>(&r[c][4 + k]));
            acc[2*k]   = fmaf(wl, a.x, fmaf(wr, b.x, acc[2*k]));
            acc[2*k+1] = fmaf(wl, a.y, fmaf(wr, b.y, acc[2*k+1]));
        }
    }
}

// ---------------- kernel A: sincos + grids 0,1 -> cols 0..39 --------------

__global__ void __launch_bounds__(256, 4)
mrif_kernel_a(const float* __restrict__ x, float* __restrict__ out, int n) {
    int i = blockIdx.x * blockDim.x + threadIdx.x;
    if (i >= n) return;

    float px = __ldg(x + 3LL * i + 0);
    float py = __ldg(x + 3LL * i + 1);
    float pz = __ldg(x + 3LL * i + 2);

    // Wave 1: grid0 loads in flight during sincos.
    TLerp t0 = prep<RES0>(g_grids + OFF0, px, py, pz);
    uint32_t r0[4][8];
    load4(t0, r0);

    float buf[40];
    {
        const float HPI = 1.57079632679489662f;
        float p[3] = {px, py, pz};
#pragma unroll
        for (int d = 0; d < 3; d++) {
            float s1, c1;
            __sincosf(HPI * p[d], &s1, &c1);
            float s2 = 2.0f * s1 * c1;
            float c2 = fmaf(-2.0f * s1, s1, 1.0f);
            float s3 = fmaf(s2, c1, c2 * s1);
            float c3 = fmaf(c2, c1, -s2 * s1);
            float s4 = 2.0f * s2 * c2;
            float c4 = fmaf(-2.0f * s2, s2, 1.0f);
            buf[0 + d]  = s1;  buf[3 + d]  = s2;  buf[6 + d]  = s3;  buf[9 + d]  = s4;
            buf[12 + d] = c1;  buf[15 + d] = c2;  buf[18 + d] = c3;  buf[21 + d] = c4;
        }
    }

    // Wave 2: grid1 loads in flight while consuming grid0.
    TLerp t1 = prep<RES1>(g_grids + OFF1, px, py, pz);
    uint32_t r1[4][8];
    load4(t1, r1);

#pragma unroll
    for (int c = 0; c < 16; c++) buf[24 + c] = 0.0f;
    accum4(t0, r0, buf + 24);
    accum4(t1, r1, buf + 32);

    // 5 consecutive .cs v8 stores: cols 0..39.
    float* orow = out + (long long)i * 56;
#pragma unroll
    for (int k = 0; k < 5; k++) stg256cs(orow + 8 * k, buf + 8 * k);
}

// ---------------- kernel B: grids 2,3 -> cols 40..55 ----------------------

__global__ void __launch_bounds__(256, 4)
mrif_kernel_b(const float* __restrict__ x, float* __restrict__ out, int n) {
    int i = blockIdx.x * blockDim.x + threadIdx.x;
    if (i >= n) return;

    float px = __ldg(x + 3LL * i + 0);
    float py = __ldg(x + 3LL * i + 1);
    float pz = __ldg(x + 3LL * i + 2);

    // Wave 1: grid2.
    TLerp t2 = prep<RES2>(g_grids + OFF2, px, py, pz);
    uint32_t r2[4][8];
    load4(t2, r2);

    // Overlap: grid3 address prep + loads.
    TLerp t3 = prep<RES3>(g_grids + OFF3, px, py, pz);
    uint32_t r3[4][8];
    load4(t3, r3);

    float buf[16];
#pragma unroll
    for (int c = 0; c < 16; c++) buf[c] = 0.0f;
    accum4(t2, r2, buf + 0);
    accum4(t3, r3, buf + 8);

    // 2 consecutive .cs v8 stores: cols 40..55.
    float* orow = out + (long long)i * 56;
    stg256cs(orow + 40, buf + 0);
    stg256cs(orow + 48, buf + 8);
}

// ---------------- launch ----------------

extern "C" void kernel_launch(void* const* d_in, const int* in_sizes, int n_in,
                              void* d_out, int out_size) {
    const float* x  = (const float*)d_in[0];
    const float* g0 = (const float*)d_in[1];
    const float* g1 = (const float*)d_in[2];
    const float* g2 = (const float*)d_in[3];
    const float* g3 = (const float*)d_in[4];
    float* out = (float*)d_out;

    int n = in_sizes[0] / 3;

    const int TT = 256;
    fused_transpose_kernel<<<(TTOT + TT - 1) / TT, TT>>>(g0, g1, g2, g3);
    mrif_kernel_a<<<(n + 255) / 256, 256>>>(x, out, n);
    mrif_kernel_b<<<(n + 255) / 256, 256>>>(x, out, n);
}

// round 15
// speedup vs baseline: 1.6962x; 1.0964x over previous
#include <cuda_runtime.h>
#include <cuda_fp16.h>
#include <cuda_bf16.h>
#include <cstdint>

// ---------------------------------------------------------------------------
// MultiResImplicitFeature R15: R8 (champion) with a register diet so
// __launch_bounds__(256,4) fits without spills:
//  - TLerp keeps 32-bit byte offsets (grids < 4GB) instead of 64-bit ptrs
//  - corner weights recomputed at accum time (store wy,wz,wx only)
// Everything else identical to R8: pair-duplicated fp16 channel-last grid
// entries (32 B), 4 x ld.global.v8 per trilerp, row[56] buffer, 7
// consecutive st.global.cs.v8 stores.
// ---------------------------------------------------------------------------

static constexpr int RES0 = 16, RES1 = 32, RES2 = 64, RES3 = 128;
static constexpr int S0 = RES0*RES0*RES0;
static constexpr int S1 = RES1*RES1*RES1;
static constexpr int S2 = RES2*RES2*RES2;
static constexpr int S3 = RES3*RES3*RES3;
static constexpr long long OFF0 = 0;
static constexpr long long OFF1 = (long long)S0*8;
static constexpr long long OFF2 = OFF1 + (long long)S1*8;
static constexpr long long OFF3 = OFF2 + (long long)S2*8;
static constexpr long long GTOTAL = OFF3 + (long long)S3*8;   // 76.7 MB

__device__ __align__(256) uint32_t g_grids[GTOTAL];

__device__ __forceinline__ void ldg256(const uint32_t* p, uint32_t r[8]) {
    asm volatile("ld.global.v8.f32 {%0,%1,%2,%3,%4,%5,%6,%7}, [%8];"
                 : "=r"(r[0]), "=r"(r[1]), "=r"(r[2]), "=r"(r[3]),
                   "=r"(r[4]), "=r"(r[5]), "=r"(r[6]), "=r"(r[7])
                 : "l"(p));
}

__device__ __forceinline__ void stg256cs(float* p, const float* v) {
    asm volatile("st.global.cs.v8.f32 [%0], {%1,%2,%3,%4,%5,%6,%7,%8};"
                 :: "l"(p), "f"(v[0]), "f"(v[1]), "f"(v[2]), "f"(v[3]),
                    "f"(v[4]), "f"(v[5]), "f"(v[6]), "f"(v[7])
                 : "memory");
}

// ---------------- fused transpose (one launch, all grids) -----------------

template <int R>
__device__ __forceinline__ void do_transpose(const float* __restrict__ in,
                                             uint32_t* __restrict__ out, int i) {
    constexpr int S = R * R * R;
    int x = i & (R - 1);
    int i2 = (x < R - 1) ? i + 1 : i;
    __half h[16];
#pragma unroll
    for (int c = 0; c < 8; c++) {
        h[c]     = __float2half(__ldcs(in + (long long)c * S + i));
        h[8 + c] = __float2half(__ldcs(in + (long long)c * S + i2));
    }
    uint4* dst = reinterpret_cast<uint4*>(out + (long long)i * 8);
    const uint4* src = reinterpret_cast<const uint4*>(h);
    dst[0] = src[0];
    dst[1] = src[1];
}

static constexpr int TTOT = S3 + S2 + S1 + S0;

__global__ void __launch_bounds__(256)
fused_transpose_kernel(const float* __restrict__ g0, const float* __restrict__ g1,
                       const float* __restrict__ g2, const float* __restrict__ g3) {
    int u = blockIdx.x * blockDim.x + threadIdx.x;
    if (u < S3) {
        do_transpose<RES3>(g3, g_grids + OFF3, u);
    } else if (u < S3 + S2) {
        do_transpose<RES2>(g2, g_grids + OFF2, u - S3);
    } else if (u < S3 + S2 + S1) {
        do_transpose<RES1>(g1, g_grids + OFF1, u - S3 - S2);
    } else if (u < TTOT) {
        do_transpose<RES0>(g0, g_grids + OFF0, u - S3 - S2 - S1);
    }
}

// ---------------- main kernel ---------------------------------------------

// Compact trilerp state: 32-bit entry offsets (in u32 units) + 3 fractions.
struct TLerp {
    uint32_t o[4];   // u32-offset of each (z,y) corner entry from g_grids
    float wy, wz, wx;
};

template <int R>
__device__ __forceinline__ TLerp prep(uint32_t base_u32,
                                      float px, float py, float pz) {
    const float scale = 0.5f * (float)(R - 1);
    float cx = (px + 1.0f) * scale;
    float cy = (py + 1.0f) * scale;
    float cz = (pz + 1.0f) * scale;
    float fx = floorf(cx), fy = floorf(cy), fz = floorf(cz);
    int x0 = (int)fx; x0 = max(0, min(x0, R - 1));
    int y0 = (int)fy; y0 = max(0, min(y0, R - 1));
    int z0 = (int)fz; z0 = max(0, min(z0, R - 1));
    int y1 = min(y0 + 1, R - 1);
    int z1 = min(z0 + 1, R - 1);

    TLerp t;
    t.wx = cx - fx;
    t.wy = cy - fy;
    t.wz = cz - fz;
    uint32_t b00 = (uint32_t)(((z0 * R + y0) * R + x0) << 3);
    uint32_t b01 = (uint32_t)(((z0 * R + y1) * R + x0) << 3);
    uint32_t b10 = (uint32_t)(((z1 * R + y0) * R + x0) << 3);
    uint32_t b11 = (uint32_t)(((z1 * R + y1) * R + x0) << 3);
    t.o[0] = base_u32 + b00;
    t.o[1] = base_u32 + b01;
    t.o[2] = base_u32 + b10;
    t.o[3] = base_u32 + b11;
    return t;
}

__device__ __forceinline__ void load4(const TLerp& t, uint32_t r[4][8]) {
#pragma unroll
    for (int c = 0; c < 4; c++) ldg256(g_grids + t.o[c], r[c]);
}

__device__ __forceinline__ void accum4(const TLerp& t, const uint32_t r[4][8],
                                       float* __restrict__ acc) {
    float wxl = 1.0f - t.wx;
    float wxr = t.wx;
    float wzy[4];
    wzy[0] = (1.0f - t.wz) * (1.0f - t.wy);
    wzy[1] = (1.0f - t.wz) * t.wy;
    wzy[2] = t.wz * (1.0f - t.wy);
    wzy[3] = t.wz * t.wy;
#pragma unroll
    for (int c = 0; c < 4; c++) {
        float wl = wzy[c] * wxl;
        float wr = wzy[c] * wxr;
#pragma unroll
        for (int k = 0; k < 4; k++) {
            float2 a = __half22float2(*reinterpret_cast<const __half2*>(&r[c][k]));
            float2 b = __half22float2(*reinterpret_cast<const __half2*>(&r[c][4 + k]));
            acc[2*k]   = fmaf(wl, a.x, fmaf(wr, b.x, acc[2*k]));
            acc[2*k+1] = fmaf(wl, a.y, fmaf(wr, b.y, acc[2*k+1]));
        }
    }
}

__global__ void __launch_bounds__(256, 4)
mrif_main_kernel(const float* __restrict__ x, float* __restrict__ out, int n) {
    int i = blockIdx.x * blockDim.x + threadIdx.x;
    if (i >= n) return;

    float px = __ldg(x + 3LL * i + 0);
    float py = __ldg(x + 3LL * i + 1);
    float pz = __ldg(x + 3LL * i + 2);

    // Phase 1: all gather state (compact: 4 u32 offsets + 3 floats each).
    TLerp t0 = prep<RES0>((uint32_t)OFF0, px, py, pz);
    TLerp t1 = prep<RES1>((uint32_t)OFF1, px, py, pz);
    TLerp t2 = prep<RES2>((uint32_t)OFF2, px, py, pz);
    TLerp t3 = prep<RES3>((uint32_t)OFF3, px, py, pz);

    // Phase 2: first load wave (grids 0,1).
    uint32_t r0[4][8], r1[4][8];
    load4(t0, r0);
    load4(t1, r1);

    // Phase 3: Fourier features (3 sincos + harmonic recurrences).
    float row[56];
    {
        const float HPI = 1.57079632679489662f;
        float p[3] = {px, py, pz};
#pragma unroll
        for (int d = 0; d < 3; d++) {
            float s1, c1;
            __sincosf(HPI * p[d], &s1, &c1);
            float s2 = 2.0f * s1 * c1;
            float c2 = fmaf(-2.0f * s1, s1, 1.0f);
            float s3 = fmaf(s2, c1, c2 * s1);
            float c3 = fmaf(c2, c1, -s2 * s1);
            float s4 = 2.0f * s2 * c2;
            float c4 = fmaf(-2.0f * s2, s2, 1.0f);
            row[0 + d]  = s1;  row[3 + d]  = s2;  row[6 + d]  = s3;  row[9 + d]  = s4;
            row[12 + d] = c1;  row[15 + d] = c2;  row[18 + d] = c3;  row[21 + d] = c4;
        }
    }
#pragma unroll
    for (int c = 0; c < 32; c++) row[24 + c] = 0.0f;

    // Phase 4: second load wave interleaved with consumption.
    uint32_t r2[4][8];
    load4(t2, r2);
    accum4(t0, r0, row + 24);
    uint32_t r3[4][8];
    load4(t3, r3);
    accum4(t1, r1, row + 32);
    accum4(t2, r2, row + 40);
    accum4(t3, r3, row + 48);

    // 7 consecutive 256-bit streaming stores.
    float* orow = out + (long long)i * 56;
#pragma unroll
    for (int k = 0; k < 7; k++) stg256cs(orow + 8 * k, row + 8 * k);
}

extern "C" void kernel_launch(void* const* d_in, const int* in_sizes, int n_in,
                              void* d_out, int out_size) {
    const float* x  = (const float*)d_in[0];
    const float* g0 = (const float*)d_in[1];
    const float* g1 = (const float*)d_in[2];
    const float* g2 = (const float*)d_in[3];
    const float* g3 = (const float*)d_in[4];
    float* out = (float*)d_out;

    int n = in_sizes[0] / 3;

    const int TT = 256;
    fused_transpose_kernel<<<(TTOT + TT - 1) / TT, TT>>>(g0, g1, g2, g3);
    mrif_main_kernel<<<(n + 255) / 256, 256>>>(x, out, n);
}